// round 11
// baseline (speedup 1.0000x reference)
#include <cuda_runtime.h>
#include <cuda_bf16.h>
#include <cstdint>

// ---------------------------------------------------------------------------
// PatchLoss: loss[n] = logsumexp_j(out[n,j]) - out[n,0]
//   out[:,0]   = cos(q_n,k_n)/T
//   out[:,1+m] = cos(q_n,k_m)/T   (diag m==n -> -10/T, exp underflows to 0)
// Fixed-shift LSE (cos <= 1):
//   loss[n] = (1 - c_nn)/T + ln( sum_{m!=n} exp((c_nm-1)/T) + exp((c_nn-1)/T) )
//
// NOTE: harness compiles via baseline compute_103 PTX (no 'a' feature set) —
// tcgen05/TMEM are NOT available. GEMM uses mma.sync HMMA (sm_80 baseline).
//
// Pipeline:
//   1) prep: fp32 norms, pos = c_nn (fp32 exact), normalized rows -> bf16.
//   2) gemm: 128x128 CTA tile, 8 warps (2x4), warp tile 64x32,
//      mma.sync.m16n8k16 bf16->fp32, K=256 in 4 cp.async chunks of 64,
//      2-stage pipeline (prefetch c+1 under compute c), 2 CTAs/SM.
//      Fused epilogue: ex2.approx((c-1)/T*log2e), diag mask, quad-reduce,
//      atomicAdd row sums.
//   3) finalize: loss[n] = (1-pos)/T + ln(rowAcc[n] + exp2((pos-1)*K2)).
// ---------------------------------------------------------------------------

#define NMAX 8192
#define DDIM 256

#define TEMP_INV 14.285714285714286f
#define K2C      20.60992915555662f   // log2(e)/0.07

#define NTHREADS 256
#define SROWB 144                      // padded smem row stride (72 bf16)
#define TILE_SM (128 * SROWB)          // 18432 B per operand tile
#define STAGE_SM (2 * TILE_SM)         // A + B per stage
#define SMEM_TOTAL (2 * STAGE_SM)      // 73728 B, two stages

static __device__ float g_pos[NMAX];
static __device__ float g_rowAcc[NMAX];
static __device__ __nv_bfloat16 g_Qbf[NMAX * DDIM];
static __device__ __nv_bfloat16 g_Kbf[NMAX * DDIM];

// ------------------------------ PTX helpers --------------------------------

__device__ __forceinline__ uint32_t smem_u32(const void* p) {
    uint32_t a;
    asm("{ .reg .u64 t; cvta.to.shared.u64 t, %1; cvt.u32.u64 %0, t; }"
        : "=r"(a) : "l"(p));
    return a;
}

__device__ __forceinline__ float ex2_approx(float x) {
    float y;
    asm("ex2.approx.ftz.f32 %0, %1;" : "=f"(y) : "f"(x));
    return y;
}

__device__ __forceinline__ void cp_async16(uint32_t saddr, const void* gptr) {
    asm volatile("cp.async.cg.shared.global [%0], [%1], 16;"
                 :: "r"(saddr), "l"(gptr) : "memory");
}
__device__ __forceinline__ void cp_async_commit() {
    asm volatile("cp.async.commit_group;" ::: "memory");
}
template <int NLeft>
__device__ __forceinline__ void cp_async_wait() {
    asm volatile("cp.async.wait_group %0;" :: "n"(NLeft) : "memory");
}

__device__ __forceinline__ void ldsm_x4(uint32_t* r, uint32_t addr) {
    asm volatile("ldmatrix.sync.aligned.m8n8.x4.shared.b16 {%0,%1,%2,%3}, [%4];"
                 : "=r"(r[0]), "=r"(r[1]), "=r"(r[2]), "=r"(r[3]) : "r"(addr));
}
__device__ __forceinline__ void ldsm_x2(uint32_t* r, uint32_t addr) {
    asm volatile("ldmatrix.sync.aligned.m8n8.x2.shared.b16 {%0,%1}, [%2];"
                 : "=r"(r[0]), "=r"(r[1]) : "r"(addr));
}

__device__ __forceinline__ void mma16816(float* d, const uint32_t* a,
                                         const uint32_t* b) {
    asm volatile(
        "mma.sync.aligned.m16n8k16.row.col.f32.bf16.bf16.f32 "
        "{%0,%1,%2,%3}, {%4,%5,%6,%7}, {%8,%9}, {%0,%1,%2,%3};"
        : "+f"(d[0]), "+f"(d[1]), "+f"(d[2]), "+f"(d[3])
        : "r"(a[0]), "r"(a[1]), "r"(a[2]), "r"(a[3]), "r"(b[0]), "r"(b[1]));
}

// ------------------------------- prep kernel -------------------------------
// One warp per row: norms, pos = cos(q_n,k_n), normalized bf16 rows.

__global__ void prep_kernel(const float* __restrict__ q,
                            const float* __restrict__ k, int N) {
    int warp = threadIdx.x >> 5;
    int lane = threadIdx.x & 31;
    int row  = blockIdx.x * 8 + warp;
    if (row >= N) return;

    const float4* qr = (const float4*)(q + (size_t)row * DDIM) + lane * 2;
    const float4* kr = (const float4*)(k + (size_t)row * DDIM) + lane * 2;
    float4 qa0 = qr[0], qa1 = qr[1];
    float4 ka0 = kr[0], ka1 = kr[1];

    float sq = qa0.x * qa0.x + qa0.y * qa0.y + qa0.z * qa0.z + qa0.w * qa0.w +
               qa1.x * qa1.x + qa1.y * qa1.y + qa1.z * qa1.z + qa1.w * qa1.w;
    float sk = ka0.x * ka0.x + ka0.y * ka0.y + ka0.z * ka0.z + ka0.w * ka0.w +
               ka1.x * ka1.x + ka1.y * ka1.y + ka1.z * ka1.z + ka1.w * ka1.w;
    float sd = qa0.x * ka0.x + qa0.y * ka0.y + qa0.z * ka0.z + qa0.w * ka0.w +
               qa1.x * ka1.x + qa1.y * ka1.y + qa1.z * ka1.z + qa1.w * ka1.w;
#pragma unroll
    for (int o = 16; o > 0; o >>= 1) {
        sq += __shfl_xor_sync(0xffffffffu, sq, o);
        sk += __shfl_xor_sync(0xffffffffu, sk, o);
        sd += __shfl_xor_sync(0xffffffffu, sd, o);
    }
    float qinv = rsqrtf(sq);
    float kinv = rsqrtf(sk);
    if (lane == 0) {
        g_pos[row]    = sd * qinv * kinv;
        g_rowAcc[row] = 0.f;
    }

    __nv_bfloat162 qb[4], kb[4];
    qb[0] = __float22bfloat162_rn(make_float2(qa0.x * qinv, qa0.y * qinv));
    qb[1] = __float22bfloat162_rn(make_float2(qa0.z * qinv, qa0.w * qinv));
    qb[2] = __float22bfloat162_rn(make_float2(qa1.x * qinv, qa1.y * qinv));
    qb[3] = __float22bfloat162_rn(make_float2(qa1.z * qinv, qa1.w * qinv));
    kb[0] = __float22bfloat162_rn(make_float2(ka0.x * kinv, ka0.y * kinv));
    kb[1] = __float22bfloat162_rn(make_float2(ka0.z * kinv, ka0.w * kinv));
    kb[2] = __float22bfloat162_rn(make_float2(ka1.x * kinv, ka1.y * kinv));
    kb[3] = __float22bfloat162_rn(make_float2(ka1.z * kinv, ka1.w * kinv));
    *(uint4*)(g_Qbf + (size_t)row * DDIM + lane * 8) = *(const uint4*)qb;
    *(uint4*)(g_Kbf + (size_t)row * DDIM + lane * 8) = *(const uint4*)kb;
}

// ------------------------------- GEMM kernel -------------------------------
// 128x128 CTA tile, warp grid 2(M) x 4(N), warp tile 64x32.
// K=256 in 4 chunks of 64 bf16 into padded smem (stride 144B), 2-stage
// cp.async pipeline. A row-major -> .row via ldmatrix x4; B stored [n][k]
// row-major = .col operand via ldmatrix x2 (non-transposed).

__device__ __forceinline__ void load_chunk(uint32_t stageA, uint32_t stageB,
                                           int arow, int brow, int c, int tid) {
#pragma unroll
    for (int t = 0; t < 4; ++t) {
        int i  = tid + t * NTHREADS;    // 0..1023
        int r  = i >> 3;                // tile row 0..127
        int c8 = i & 7;                 // 16B unit 0..7
        const char* gA = (const char*)(g_Qbf + (size_t)(arow + r) * DDIM
                                       + c * 64 + c8 * 8);
        const char* gB = (const char*)(g_Kbf + (size_t)(brow + r) * DDIM
                                       + c * 64 + c8 * 8);
        uint32_t soff = (uint32_t)(r * SROWB + c8 * 16);
        cp_async16(stageA + soff, gA);
        cp_async16(stageB + soff, gB);
    }
    cp_async_commit();
}

__global__ void __launch_bounds__(NTHREADS, 2) gemm_kernel(int N) {
    extern __shared__ __align__(16) char smem[];
    const uint32_t sb = smem_u32(smem);

    const int tid  = threadIdx.x;
    const int wid  = tid >> 5;
    const int lane = tid & 31;
    const int wm   = wid >> 2;   // 0..1  (M)
    const int wn   = wid & 3;    // 0..3  (N)

    const int arow = blockIdx.x * 128;
    const int brow = blockIdx.y * 128;

    // ldmatrix per-lane offsets (bytes within an operand tile)
    const uint32_t aoff = (uint32_t)(((lane & 7) + 8 * ((lane >> 3) & 1)) * SROWB
                                     + (lane >> 4) * 16);
    const uint32_t boff = (uint32_t)((lane & 7) * SROWB + ((lane >> 3) & 1) * 16);

    float acc[4][4][4] = {};   // [am][an][reg]

    load_chunk(sb, sb + TILE_SM, arow, brow, 0, tid);   // stage 0, chunk 0

    for (int c = 0; c < 4; ++c) {
        const uint32_t curA = sb + (uint32_t)((c & 1) * STAGE_SM);
        const uint32_t curB = curA + TILE_SM;
        if (c < 3) {
            const uint32_t nxtA = sb + (uint32_t)(((c + 1) & 1) * STAGE_SM);
            load_chunk(nxtA, nxtA + TILE_SM, arow, brow, c + 1, tid);
            cp_async_wait<1>();            // chunk c landed; c+1 in flight
        } else {
            cp_async_wait<0>();
        }
        __syncthreads();

#pragma unroll
        for (int ks = 0; ks < 4; ++ks) {    // k-step of 16 within chunk
            uint32_t afrag[4][4], bfrag[4][2];
#pragma unroll
            for (int am = 0; am < 4; am++)
                ldsm_x4(afrag[am],
                        curA + (uint32_t)((wm * 64 + am * 16) * SROWB) + ks * 32 + aoff);
#pragma unroll
            for (int an = 0; an < 4; an++)
                ldsm_x2(bfrag[an],
                        curB + (uint32_t)((wn * 32 + an * 8) * SROWB) + ks * 32 + boff);
#pragma unroll
            for (int am = 0; am < 4; am++)
#pragma unroll
                for (int an = 0; an < 4; an++)
                    mma16816(acc[am][an], afrag[am], bfrag[an]);
        }
        __syncthreads();                    // stage reusable for chunk c+2
    }

    // Epilogue: c-fragment rows r0 = m0 + lane/4, r1 = r0 + 8;
    // cols = n0 + (lane%4)*2 + {0,1}. exp-transform, diag mask, quad reduce.
#pragma unroll
    for (int am = 0; am < 4; am++) {
        const int r0 = arow + wm * 64 + am * 16 + (lane >> 2);
        const int r1 = r0 + 8;
        float s0 = 0.f, s1 = 0.f;
#pragma unroll
        for (int an = 0; an < 4; an++) {
            const int gc = brow + wn * 32 + an * 8 + (lane & 3) * 2;
            float t0 = ex2_approx(fmaf(acc[am][an][0], K2C, -K2C));
            float t1 = ex2_approx(fmaf(acc[am][an][1], K2C, -K2C));
            float t2 = ex2_approx(fmaf(acc[am][an][2], K2C, -K2C));
            float t3 = ex2_approx(fmaf(acc[am][an][3], K2C, -K2C));
            if (gc == r0)     t0 = 0.f;     // diag -> exp(-10/T) ~ 0
            if (gc + 1 == r0) t1 = 0.f;
            if (gc == r1)     t2 = 0.f;
            if (gc + 1 == r1) t3 = 0.f;
            s0 += t0 + t1;
            s1 += t2 + t3;
        }
        s0 += __shfl_xor_sync(0xffffffffu, s0, 1);
        s0 += __shfl_xor_sync(0xffffffffu, s0, 2);
        s1 += __shfl_xor_sync(0xffffffffu, s1, 1);
        s1 += __shfl_xor_sync(0xffffffffu, s1, 2);
        if ((lane & 3) == 0) {
            atomicAdd(&g_rowAcc[r0], s0);
            atomicAdd(&g_rowAcc[r1], s1);
        }
    }
}

// ------------------------------ finalize -----------------------------------

__global__ void finalize_kernel(float* __restrict__ out, int N) {
    int n = blockIdx.x * 256 + threadIdx.x;
    if (n >= N) return;
    float pos   = g_pos[n];
    float total = g_rowAcc[n] + exp2f((pos - 1.0f) * K2C);
    out[n] = TEMP_INV * (1.0f - pos) + logf(total);
}

// ------------------------------ launcher -----------------------------------

extern "C" void kernel_launch(void* const* d_in, const int* in_sizes, int n_in,
                              void* d_out, int out_size) {
    const float* q = (const float*)d_in[0];
    const float* k = (const float*)d_in[1];
    const int N = in_sizes[0] / DDIM;

    prep_kernel<<<(N + 7) / 8, 256>>>(q, k, N);

    cudaFuncSetAttribute(gemm_kernel,
                         cudaFuncAttributeMaxDynamicSharedMemorySize,
                         SMEM_TOTAL);
    dim3 grid(N / 128, N / 128);
    gemm_kernel<<<grid, NTHREADS, SMEM_TOTAL>>>(N);

    finalize_kernel<<<(N + 255) / 256, 256>>>((float*)d_out, N);
}

// round 17
// speedup vs baseline: 1.0196x; 1.0196x over previous
#include <cuda_runtime.h>
#include <cuda_bf16.h>
#include <cstdint>

// ---------------------------------------------------------------------------
// PatchLoss: loss[n] = logsumexp_j(out[n,j]) - out[n,0]
// Fixed-shift LSE (cos <= 1):
//   loss[n] = (1 - c_nn)/T + ln( sum_{m!=n} exp((c_nm-1)/T) + exp((c_nn-1)/T) )
//
// Baseline-PTX only (harness targets compute_103): mma.sync HMMA path.
//
//   1) prep: fp32 norms, pos = c_nn, normalized rows -> bf16.
//   2) gemm: 128x128 CTA tile, 4 warps (2x2), warp tile 64x64,
//      mma.sync.m16n8k16 bf16->fp32, K=256 in 4 cp.async chunks of 64,
//      2-stage pipeline, 2 CTAs/SM (128-thread CTAs -> 256 regs/thread).
//      Fused epilogue: ex2.approx, diag mask, quad-reduce, atomicAdd rows.
//   3) finalize: loss[n] = (1-pos)/T + ln(rowAcc[n] + exp2((pos-1)*K2)).
// ---------------------------------------------------------------------------

#define NMAX 8192
#define DDIM 256

#define TEMP_INV 14.285714285714286f
#define K2C      20.60992915555662f   // log2(e)/0.07

#define NTHREADS 128
#define SROWB 144                      // padded smem row stride (72 bf16)
#define TILE_SM (128 * SROWB)          // 18432 B per operand tile
#define STAGE_SM (2 * TILE_SM)         // A + B per stage
#define SMEM_TOTAL (2 * STAGE_SM)      // 73728 B, two stages

static __device__ float g_pos[NMAX];
static __device__ float g_rowAcc[NMAX];
static __device__ __nv_bfloat16 g_Qbf[NMAX * DDIM];
static __device__ __nv_bfloat16 g_Kbf[NMAX * DDIM];

// ------------------------------ PTX helpers --------------------------------

__device__ __forceinline__ uint32_t smem_u32(const void* p) {
    uint32_t a;
    asm("{ .reg .u64 t; cvta.to.shared.u64 t, %1; cvt.u32.u64 %0, t; }"
        : "=r"(a) : "l"(p));
    return a;
}

__device__ __forceinline__ float ex2_approx(float x) {
    float y;
    asm("ex2.approx.ftz.f32 %0, %1;" : "=f"(y) : "f"(x));
    return y;
}

__device__ __forceinline__ void cp_async16(uint32_t saddr, const void* gptr) {
    asm volatile("cp.async.cg.shared.global [%0], [%1], 16;"
                 :: "r"(saddr), "l"(gptr) : "memory");
}
__device__ __forceinline__ void cp_async_commit() {
    asm volatile("cp.async.commit_group;" ::: "memory");
}
template <int NLeft>
__device__ __forceinline__ void cp_async_wait() {
    asm volatile("cp.async.wait_group %0;" :: "n"(NLeft) : "memory");
}

__device__ __forceinline__ void ldsm_x4(uint32_t* r, uint32_t addr) {
    asm volatile("ldmatrix.sync.aligned.m8n8.x4.shared.b16 {%0,%1,%2,%3}, [%4];"
                 : "=r"(r[0]), "=r"(r[1]), "=r"(r[2]), "=r"(r[3]) : "r"(addr));
}

__device__ __forceinline__ void mma16816(float* d, const uint32_t* a,
                                         const uint32_t* b) {
    asm volatile(
        "mma.sync.aligned.m16n8k16.row.col.f32.bf16.bf16.f32 "
        "{%0,%1,%2,%3}, {%4,%5,%6,%7}, {%8,%9}, {%0,%1,%2,%3};"
        : "+f"(d[0]), "+f"(d[1]), "+f"(d[2]), "+f"(d[3])
        : "r"(a[0]), "r"(a[1]), "r"(a[2]), "r"(a[3]), "r"(b[0]), "r"(b[1]));
}

// ------------------------------- prep kernel -------------------------------

__global__ void prep_kernel(const float* __restrict__ q,
                            const float* __restrict__ k, int N) {
    int warp = threadIdx.x >> 5;
    int lane = threadIdx.x & 31;
    int row  = blockIdx.x * 8 + warp;
    if (row >= N) return;

    const float4* qr = (const float4*)(q + (size_t)row * DDIM) + lane * 2;
    const float4* kr = (const float4*)(k + (size_t)row * DDIM) + lane * 2;
    float4 qa0 = qr[0], qa1 = qr[1];
    float4 ka0 = kr[0], ka1 = kr[1];

    float sq = qa0.x * qa0.x + qa0.y * qa0.y + qa0.z * qa0.z + qa0.w * qa0.w +
               qa1.x * qa1.x + qa1.y * qa1.y + qa1.z * qa1.z + qa1.w * qa1.w;
    float sk = ka0.x * ka0.x + ka0.y * ka0.y + ka0.z * ka0.z + ka0.w * ka0.w +
               ka1.x * ka1.x + ka1.y * ka1.y + ka1.z * ka1.z + ka1.w * ka1.w;
    float sd = qa0.x * ka0.x + qa0.y * ka0.y + qa0.z * ka0.z + qa0.w * ka0.w +
               qa1.x * ka1.x + qa1.y * ka1.y + qa1.z * ka1.z + qa1.w * ka1.w;
#pragma unroll
    for (int o = 16; o > 0; o >>= 1) {
        sq += __shfl_xor_sync(0xffffffffu, sq, o);
        sk += __shfl_xor_sync(0xffffffffu, sk, o);
        sd += __shfl_xor_sync(0xffffffffu, sd, o);
    }
    float qinv = rsqrtf(sq);
    float kinv = rsqrtf(sk);
    if (lane == 0) {
        g_pos[row]    = sd * qinv * kinv;
        g_rowAcc[row] = 0.f;
    }

    __nv_bfloat162 qb[4], kb[4];
    qb[0] = __float22bfloat162_rn(make_float2(qa0.x * qinv, qa0.y * qinv));
    qb[1] = __float22bfloat162_rn(make_float2(qa0.z * qinv, qa0.w * qinv));
    qb[2] = __float22bfloat162_rn(make_float2(qa1.x * qinv, qa1.y * qinv));
    qb[3] = __float22bfloat162_rn(make_float2(qa1.z * qinv, qa1.w * qinv));
    kb[0] = __float22bfloat162_rn(make_float2(ka0.x * kinv, ka0.y * kinv));
    kb[1] = __float22bfloat162_rn(make_float2(ka0.z * kinv, ka0.w * kinv));
    kb[2] = __float22bfloat162_rn(make_float2(ka1.x * kinv, ka1.y * kinv));
    kb[3] = __float22bfloat162_rn(make_float2(ka1.z * kinv, ka1.w * kinv));
    *(uint4*)(g_Qbf + (size_t)row * DDIM + lane * 8) = *(const uint4*)qb;
    *(uint4*)(g_Kbf + (size_t)row * DDIM + lane * 8) = *(const uint4*)kb;
}

// ------------------------------- GEMM kernel -------------------------------
// 128x128 CTA tile, 4 warps (2x2), warp tile 64x64.
// K=256 in 4 chunks of 64 bf16 (padded smem stride 144B), 2-stage cp.async.
// A row-major -> .row via ldmatrix x4; B stored [n][k] row-major = .col
// operand, two n-fragments per ldmatrix x4 (paired load).

__device__ __forceinline__ void load_chunk(uint32_t stageA, uint32_t stageB,
                                           int arow, int brow, int c, int tid) {
#pragma unroll
    for (int t = 0; t < 8; ++t) {
        int i  = tid + t * NTHREADS;    // 0..1023
        int r  = i >> 3;                // tile row 0..127
        int c8 = i & 7;                 // 16B unit 0..7
        const char* gA = (const char*)(g_Qbf + (size_t)(arow + r) * DDIM
                                       + c * 64 + c8 * 8);
        const char* gB = (const char*)(g_Kbf + (size_t)(brow + r) * DDIM
                                       + c * 64 + c8 * 8);
        uint32_t soff = (uint32_t)(r * SROWB + c8 * 16);
        cp_async16(stageA + soff, gA);
        cp_async16(stageB + soff, gB);
    }
    cp_async_commit();
}

__global__ void __launch_bounds__(NTHREADS, 2) gemm_kernel(int N) {
    extern __shared__ __align__(16) char smem[];
    const uint32_t sb = smem_u32(smem);

    const int tid  = threadIdx.x;
    const int wid  = tid >> 5;
    const int lane = tid & 31;
    const int wm   = wid >> 1;   // 0..1  (M half)
    const int wn   = wid & 1;    // 0..1  (N half)

    const int arow = blockIdx.x * 128;
    const int brow = blockIdx.y * 128;

    // A x4 lane offset: g=lane>>3: 0:(m0-7,k0) 1:(m8-15,k0) 2:(m0-7,k8) 3:(m8-15,k8)
    const uint32_t aoff = (uint32_t)(((lane & 7) + 8 * ((lane >> 3) & 1)) * SROWB
                                     + (lane >> 4) * 16);
    // B paired x4: g=lane>>3: 0:(n0-7,k0) 1:(n0-7,k8) 2:(n8-15,k0) 3:(n8-15,k8)
    const uint32_t boff = (uint32_t)(((lane & 7) + 8 * (lane >> 4)) * SROWB
                                     + ((lane >> 3) & 1) * 16);

    float acc[4][8][4] = {};   // [am][an][reg]

    load_chunk(sb, sb + TILE_SM, arow, brow, 0, tid);   // stage 0, chunk 0

    for (int c = 0; c < 4; ++c) {
        const uint32_t curA = sb + (uint32_t)((c & 1) * STAGE_SM);
        const uint32_t curB = curA + TILE_SM;
        if (c < 3) {
            const uint32_t nxtA = sb + (uint32_t)(((c + 1) & 1) * STAGE_SM);
            load_chunk(nxtA, nxtA + TILE_SM, arow, brow, c + 1, tid);
            cp_async_wait<1>();            // chunk c landed; c+1 in flight
        } else {
            cp_async_wait<0>();
        }
        __syncthreads();

#pragma unroll
        for (int ks = 0; ks < 4; ++ks) {    // k-step of 16 within chunk
            uint32_t afrag[4][4], bfrag[8][2];
#pragma unroll
            for (int am = 0; am < 4; am++)
                ldsm_x4(afrag[am],
                        curA + (uint32_t)((wm * 64 + am * 16) * SROWB) + ks * 32 + aoff);
#pragma unroll
            for (int p = 0; p < 4; p++) {   // pair p covers an=2p, 2p+1
                uint32_t t4[4];
                ldsm_x4(t4, curB + (uint32_t)((wn * 64 + p * 16) * SROWB) + ks * 32 + boff);
                bfrag[2 * p][0]     = t4[0];
                bfrag[2 * p][1]     = t4[1];
                bfrag[2 * p + 1][0] = t4[2];
                bfrag[2 * p + 1][1] = t4[3];
            }
#pragma unroll
            for (int am = 0; am < 4; am++)
#pragma unroll
                for (int an = 0; an < 8; an++)
                    mma16816(acc[am][an], afrag[am], bfrag[an]);
        }
        __syncthreads();                    // stage reusable for chunk c+2
    }

    // Epilogue: rows r0 = m0 + lane/4, r1 = r0 + 8;
    // cols = n0 + an*8 + (lane%4)*2 + {0,1}. exp, diag mask, quad reduce.
#pragma unroll
    for (int am = 0; am < 4; am++) {
        const int r0 = arow + wm * 64 + am * 16 + (lane >> 2);
        const int r1 = r0 + 8;
        float s0 = 0.f, s1 = 0.f;
#pragma unroll
        for (int an = 0; an < 8; an++) {
            const int gc = brow + wn * 64 + an * 8 + (lane & 3) * 2;
            float t0 = ex2_approx(fmaf(acc[am][an][0], K2C, -K2C));
            float t1 = ex2_approx(fmaf(acc[am][an][1], K2C, -K2C));
            float t2 = ex2_approx(fmaf(acc[am][an][2], K2C, -K2C));
            float t3 = ex2_approx(fmaf(acc[am][an][3], K2C, -K2C));
            if (gc == r0)     t0 = 0.f;     // diag -> exp(-10/T) ~ 0
            if (gc + 1 == r0) t1 = 0.f;
            if (gc == r1)     t2 = 0.f;
            if (gc + 1 == r1) t3 = 0.f;
            s0 += t0 + t1;
            s1 += t2 + t3;
        }
        s0 += __shfl_xor_sync(0xffffffffu, s0, 1);
        s0 += __shfl_xor_sync(0xffffffffu, s0, 2);
        s1 += __shfl_xor_sync(0xffffffffu, s1, 1);
        s1 += __shfl_xor_sync(0xffffffffu, s1, 2);
        if ((lane & 3) == 0) {
            atomicAdd(&g_rowAcc[r0], s0);
            atomicAdd(&g_rowAcc[r1], s1);
        }
    }
}

// ------------------------------ finalize -----------------------------------

__global__ void finalize_kernel(float* __restrict__ out, int N) {
    int n = blockIdx.x * 256 + threadIdx.x;
    if (n >= N) return;
    float pos   = g_pos[n];
    float total = g_rowAcc[n] + exp2f((pos - 1.0f) * K2C);
    out[n] = TEMP_INV * (1.0f - pos) + logf(total);
}

// ------------------------------ launcher -----------------------------------

extern "C" void kernel_launch(void* const* d_in, const int* in_sizes, int n_in,
                              void* d_out, int out_size) {
    const float* q = (const float*)d_in[0];
    const float* k = (const float*)d_in[1];
    const int N = in_sizes[0] / DDIM;

    prep_kernel<<<(N + 7) / 8, 256>>>(q, k, N);

    cudaFuncSetAttribute(gemm_kernel,
                         cudaFuncAttributeMaxDynamicSharedMemorySize,
                         SMEM_TOTAL);
    dim3 grid(N / 128, N / 128);
    gemm_kernel<<<grid, NTHREADS, SMEM_TOTAL>>>(N);

    finalize_kernel<<<(N + 255) / 256, 256>>>((float*)d_out, N);
}